// round 15
// baseline (speedup 1.0000x reference)
#include <cuda_runtime.h>

// Depthwise Conv1d: B=32, C=128, L=8192, kernel=3, stride=1, pad=1, fp32.
// out[b,c,l] = w[c,0]*x[b,c,l-1] + w[c,1]*x[b,c,l] + w[c,2]*x[b,c,l+1] + bias[c]
//
// R15 = R4's winning layout (grid-strided, per-instruction coalesced,
// front-batched loads, halo scalars as L1 hits, per-iteration taps) but
// with 256-bit vector memory ops (ld/st.global.v8.f32, sm_100a-family).
// Same 64B of in-flight data per thread as R4, but half the vector
// instructions, half the halo loads, half the index ALU.

#define BATCH 32
#define CHANS 128
#define LEN   8192
#define LEN8  (LEN / 8)          // 1024 float8 per row
#define ROWS  (BATCH * CHANS)    // 4096
#define NTHREADS 256
#define ITER 2
#define TOTAL8   (ROWS * LEN8)               // 4,194,304 float8
#define NTHREADS_TOTAL (TOTAL8 / ITER)       // 2,097,152
#define NBLOCKS  (NTHREADS_TOTAL / NTHREADS) // 8192

__device__ __forceinline__ void ldg256(const float* p, float r[8]) {
    asm volatile("ld.global.v8.f32 {%0,%1,%2,%3,%4,%5,%6,%7}, [%8];"
                 : "=f"(r[0]), "=f"(r[1]), "=f"(r[2]), "=f"(r[3]),
                   "=f"(r[4]), "=f"(r[5]), "=f"(r[6]), "=f"(r[7])
                 : "l"(p));
}

__device__ __forceinline__ void stg256(float* p, const float r[8]) {
    asm volatile("st.global.v8.f32 [%0], {%1,%2,%3,%4,%5,%6,%7,%8};"
                 :: "l"(p),
                    "f"(r[0]), "f"(r[1]), "f"(r[2]), "f"(r[3]),
                    "f"(r[4]), "f"(r[5]), "f"(r[6]), "f"(r[7])
                 : "memory");
}

__global__ __launch_bounds__(NTHREADS)
void dwconv1d_kernel(const float* __restrict__ x,
                     const float* __restrict__ w,
                     const float* __restrict__ bias,
                     float* __restrict__ out)
{
    const unsigned int gid    = blockIdx.x * NTHREADS + threadIdx.x;
    const unsigned int stride = NTHREADS_TOTAL; // grid stride in float8 units

    unsigned int idx[ITER], row[ITER], j[ITER], c[ITER];
#pragma unroll
    for (int i = 0; i < ITER; i++) {
        idx[i] = gid + i * stride;
        row[i] = idx[i] >> 10;         // / LEN8
        j[i]   = idx[i] & (LEN8 - 1);  // within-row float8 index
        c[i]   = row[i] & (CHANS - 1);
    }

    // ---- front-batched 256-bit loads (2 outstanding LDG.256, coalesced) ----
    float v[ITER][8];
#pragma unroll
    for (int i = 0; i < ITER; i++)
        ldg256(x + 8u * (size_t)idx[i], v[i]);

    // ---- halo scalars (L1 hits) ----
    float left[ITER], right[ITER];
#pragma unroll
    for (int i = 0; i < ITER; i++) {
        const float* xe = x + 8u * (size_t)idx[i];
        left[i]  = (j[i] == 0)        ? 0.0f : __ldg(xe - 1);
        right[i] = (j[i] == LEN8 - 1) ? 0.0f : __ldg(xe + 8);
    }

    // ---- per-channel taps (uniform within warp -> L1 broadcast) ----
    float w0[ITER], w1[ITER], w2[ITER], bb[ITER];
#pragma unroll
    for (int i = 0; i < ITER; i++) {
        w0[i] = __ldg(&w[c[i] * 3 + 0]);
        w1[i] = __ldg(&w[c[i] * 3 + 1]);
        w2[i] = __ldg(&w[c[i] * 3 + 2]);
        bb[i] = __ldg(&bias[c[i]]);
    }

    // ---- compute + 256-bit stores ----
#pragma unroll
    for (int i = 0; i < ITER; i++) {
        float e[10];
        e[0] = left[i];
#pragma unroll
        for (int k = 0; k < 8; k++) e[k + 1] = v[i][k];
        e[9] = right[i];

        float o[8];
#pragma unroll
        for (int k = 0; k < 8; k++)
            o[k] = fmaf(w0[i], e[k], fmaf(w1[i], e[k + 1], fmaf(w2[i], e[k + 2], bb[i])));

        stg256(out + 8u * (size_t)idx[i], o);
    }
}

extern "C" void kernel_launch(void* const* d_in, const int* in_sizes, int n_in,
                              void* d_out, int out_size)
{
    const float* x    = (const float*)d_in[0];
    const float* w    = (const float*)d_in[1];
    const float* bias = (const float*)d_in[2];
    float* out        = (float*)d_out;

    dwconv1d_kernel<<<NBLOCKS, NTHREADS>>>(x, w, bias, out);
}

// round 16
// speedup vs baseline: 1.0360x; 1.0360x over previous
#include <cuda_runtime.h>

// Depthwise Conv1d: B=32, C=128, L=8192, kernel=3, stride=1, pad=1, fp32.
// out[b,c,l] = w[c,0]*x[b,c,l-1] + w[c,1]*x[b,c,l] + w[c,2]*x[b,c,l+1] + bias[c]
//
// R16 = R15 (256-bit ld/st.global.v8.f32, grid-strided ITER=2 — best kernel
// time so far at 36.1us) with redundant work removed: the grid stride is
// exactly 2048 rows (multiple of CHANS), so both iterations share the same
// channel AND the same within-row position j. Taps are loaded once (4 LDGs
// instead of 8), j/edge predicates computed once.

#define BATCH 32
#define CHANS 128
#define LEN   8192
#define LEN8  (LEN / 8)          // 1024 float8 per row
#define ROWS  (BATCH * CHANS)    // 4096
#define NTHREADS 256
#define ITER 2
#define TOTAL8   (ROWS * LEN8)               // 4,194,304 float8
#define NTHREADS_TOTAL (TOTAL8 / ITER)       // 2,097,152
#define NBLOCKS  (NTHREADS_TOTAL / NTHREADS) // 8192
// stride rows = NTHREADS_TOTAL / LEN8 = 2048 (multiple of CHANS)

__device__ __forceinline__ void ldg256(const float* p, float r[8]) {
    asm volatile("ld.global.v8.f32 {%0,%1,%2,%3,%4,%5,%6,%7}, [%8];"
                 : "=f"(r[0]), "=f"(r[1]), "=f"(r[2]), "=f"(r[3]),
                   "=f"(r[4]), "=f"(r[5]), "=f"(r[6]), "=f"(r[7])
                 : "l"(p));
}

__device__ __forceinline__ void stg256(float* p, const float r[8]) {
    asm volatile("st.global.v8.f32 [%0], {%1,%2,%3,%4,%5,%6,%7,%8};"
                 :: "l"(p),
                    "f"(r[0]), "f"(r[1]), "f"(r[2]), "f"(r[3]),
                    "f"(r[4]), "f"(r[5]), "f"(r[6]), "f"(r[7])
                 : "memory");
}

__global__ __launch_bounds__(NTHREADS)
void dwconv1d_kernel(const float* __restrict__ x,
                     const float* __restrict__ w,
                     const float* __restrict__ bias,
                     float* __restrict__ out)
{
    const unsigned int gid    = blockIdx.x * NTHREADS + threadIdx.x;
    const unsigned int stride = NTHREADS_TOTAL; // grid stride in float8 units

    // j and channel identical across both iterations (stride = 2048 rows)
    const unsigned int j = gid & (LEN8 - 1);
    const unsigned int c = (gid >> 10) & (CHANS - 1);
    const bool has_left  = (j != 0);
    const bool has_right = (j != LEN8 - 1);

    // ---- front-batched 256-bit loads (2 outstanding LDG.256, coalesced) ----
    float v[ITER][8];
#pragma unroll
    for (int i = 0; i < ITER; i++)
        ldg256(x + 8u * (size_t)(gid + i * stride), v[i]);

    // ---- halo scalars (L1 hits) ----
    float left[ITER], right[ITER];
#pragma unroll
    for (int i = 0; i < ITER; i++) {
        const float* xe = x + 8u * (size_t)(gid + i * stride);
        left[i]  = has_left  ? __ldg(xe - 1) : 0.0f;
        right[i] = has_right ? __ldg(xe + 8) : 0.0f;
    }

    // ---- per-channel taps, loaded ONCE (uniform within warp -> broadcast) ----
    const float w0 = __ldg(&w[c * 3 + 0]);
    const float w1 = __ldg(&w[c * 3 + 1]);
    const float w2 = __ldg(&w[c * 3 + 2]);
    const float bb = __ldg(&bias[c]);

    // ---- compute + 256-bit stores ----
#pragma unroll
    for (int i = 0; i < ITER; i++) {
        float e[10];
        e[0] = left[i];
#pragma unroll
        for (int k = 0; k < 8; k++) e[k + 1] = v[i][k];
        e[9] = right[i];

        float o[8];
#pragma unroll
        for (int k = 0; k < 8; k++)
            o[k] = fmaf(w0, e[k], fmaf(w1, e[k + 1], fmaf(w2, e[k + 2], bb)));

        stg256(out + 8u * (size_t)(gid + i * stride), o);
    }
}

extern "C" void kernel_launch(void* const* d_in, const int* in_sizes, int n_in,
                              void* d_out, int out_size)
{
    const float* x    = (const float*)d_in[0];
    const float* w    = (const float*)d_in[1];
    const float* bias = (const float*)d_in[2];
    float* out        = (float*)d_out;

    dwconv1d_kernel<<<NBLOCKS, NTHREADS>>>(x, w, bias, out);
}